// round 10
// baseline (speedup 1.0000x reference)
#include <cuda_runtime.h>
#include <math.h>
#include <stdint.h>

#define N_TOK 16384
#define DIM   2048
#define NEXP  64
#define KSEL  9
#define EPS_C 0.01f
#define INV_SIG_SQRT2 45.254833995939045f

#define BM 112
#define GRID 147                   // ceil(16384/112)
#define BK 32
#define NCHUNK (DIM / BK)          // 64
#define NSTAGE 6
#define XTS 36                     // x smem row stride (u32)
#define XTILE (BM * XTS)           // 4032 u32
#define WTILE (BK * 128)           // 4096 u32
#define STAGEU (XTILE + WTILE)     // 8128 u32 = 32512 B
#define SMEM_BYTES (NSTAGE * STAGEU * 4)   // 195072 B
#define XV4 (BM * 8)               // 896 float4 per x stage

// logits scratch: [row][128] (0-63 raw dot, 64-127 noise-pre dot) = 8 MB
__device__ __align__(16) float g_lg[(size_t)N_TOK * 128];

__device__ __forceinline__ unsigned long long pack_dup(float a) {
    unsigned long long r;
    unsigned ai = __float_as_uint(a);
    asm("mov.b64 %0, {%1, %1};" : "=l"(r) : "r"(ai));
    return r;
}
__device__ __forceinline__ uint32_t smem_u32(const void* p) {
    uint32_t a;
    asm("{ .reg .u64 t; cvta.to.shared.u64 t, %1; cvt.u32.u64 %0, t; }"
        : "=r"(a) : "l"(p));
    return a;
}
__device__ __forceinline__ void cp16(uint32_t dst, const void* src) {
    asm volatile("cp.async.ca.shared.global [%0], [%1], 16;"
                 :: "r"(dst), "l"(src) : "memory");
}

// ---------------- GEMM: fp32 FFMA2, 112x128 per CTA, 147 CTAs (1/SM) ----------------
extern "C" __global__ void __launch_bounds__(256, 1)
gemm_kernel(const float* __restrict__ x, const float* __restrict__ Wr,
            const float* __restrict__ Wn)
{
    extern __shared__ uint32_t smu[];
    const uint32_t sbase = smem_u32(smu);
    const int tid = threadIdx.x;
    const int ty  = tid >> 4;        // 0..15 -> rows 7ty..7ty+6
    const int tx  = tid & 15;        // col pairs 2tx+32j
    const int row0 = blockIdx.x * BM;

    // ---- x cp.async map: 896 float4 over 256 threads x 4 iters (guarded) ----
    const float* xsrc[4];
    uint32_t     xoff[4];
    bool         xact[4];
    #pragma unroll
    for (int i = 0; i < 4; i++) {
        int idx = tid + 256 * i;
        xact[i] = (idx < XV4);
        int r = idx >> 3, seg = idx & 7;
        if (!xact[i]) { r = 0; seg = 0; }
        int grow = row0 + r; if (grow > N_TOK - 1) grow = N_TOK - 1;  // tail clamp
        xsrc[i] = x + (size_t)grow * DIM + seg * 4;
        xoff[i] = (uint32_t)((r * XTS + seg * 4) * 4);
    }
    // ---- W cp.async map ----
    const int wk = tid >> 5, wq = tid & 31;
    const int wcol = wq * 4;
    const float* wsrcbase = (wcol < 64) ? (Wr + wcol) : (Wn + wcol - 64);

    unsigned long long acc[7][4];
    #pragma unroll
    for (int i = 0; i < 7; i++)
        #pragma unroll
        for (int j = 0; j < 4; j++) acc[i][j] = 0ULL;

    auto issue = [&](int c) {
        uint32_t buf = sbase + (uint32_t)((c % NSTAGE) * STAGEU * 4);
        #pragma unroll
        for (int i = 0; i < 4; i++)
            if (xact[i]) cp16(buf + xoff[i], xsrc[i] + c * BK);
        #pragma unroll
        for (int i = 0; i < 4; i++) {
            int kk = wk + 8 * i;
            cp16(buf + (uint32_t)((XTILE + kk * 128 + wcol) * 4),
                 wsrcbase + (size_t)(c * BK + kk) * NEXP);
        }
    };
    auto compute = [&](int c) {
        const uint32_t* buf = smu + (c % NSTAGE) * STAGEU;
        const float* xs = (const float*)buf;
        const float* ws = (const float*)(buf + XTILE);
        #pragma unroll 4
        for (int kk = 0; kk < BK; kk++) {
            unsigned long long b2[4];
            #pragma unroll
            for (int j = 0; j < 4; j++)
                b2[j] = *(const unsigned long long*)(ws + kk * 128 + 2 * tx + 32 * j);
            unsigned long long a2[7];
            #pragma unroll
            for (int i = 0; i < 7; i++)
                a2[i] = pack_dup(xs[(7 * ty + i) * XTS + kk]);
            #pragma unroll
            for (int i = 0; i < 7; i++)
                #pragma unroll
                for (int j = 0; j < 4; j++)
                    asm("fma.rn.f32x2 %0, %1, %2, %0;"
                        : "+l"(acc[i][j]) : "l"(a2[i]), "l"(b2[j]));
        }
    };

    // prologue: chunks 0..3 (one commit group each)
    #pragma unroll
    for (int p = 0; p < 4; p++) {
        issue(p);
        asm volatile("cp.async.commit_group;" ::: "memory");
    }

    // main loop: 2 chunks per barrier, 6-stage ring
    #pragma unroll 1
    for (int c = 0; c < NCHUNK; c += 2) {
        if (c < NCHUNK - 2)
            asm volatile("cp.async.wait_group 2;" ::: "memory");
        else
            asm volatile("cp.async.wait_group 0;" ::: "memory");
        __syncthreads();
        if (c + 4 < NCHUNK) {
            issue(c + 4);                       // stage (c-2)%6: readers passed barrier
            asm volatile("cp.async.commit_group;" ::: "memory");
        }
        if (c + 5 < NCHUNK) {
            issue(c + 5);                       // stage (c-1)%6: readers passed barrier
            asm volatile("cp.async.commit_group;" ::: "memory");
        }
        compute(c);
        compute(c + 1);
    }

    // ---- write logits (STG.64, coalesced); guard tail CTA ----
    #pragma unroll
    for (int i = 0; i < 7; i++) {
        int row = row0 + 7 * ty + i;
        if (row < N_TOK) {
            #pragma unroll
            for (int j = 0; j < 4; j++)
                *(unsigned long long*)(g_lg + (size_t)row * 128 + 2 * tx + 32 * j)
                    = acc[i][j];
        }
    }
}

// ---------------- epilogue: 1 row per warp, redux-based top-9 ----------------
__device__ __forceinline__ uint32_t redux_max(uint32_t v) {
    uint32_t r;
    asm("redux.sync.max.u32 %0, %1, 0xffffffff;" : "=r"(r) : "r"(v));
    return r;
}
__device__ __forceinline__ uint32_t ordkey(float f) {
    uint32_t u = __float_as_uint(f);
    return ((int)u < 0) ? ~u : (u | 0x80000000u);
}
__device__ __forceinline__ float ordinv(uint32_t k) {
    return __uint_as_float(((int)k < 0) ? (k ^ 0x80000000u) : ~k);
}
__device__ __forceinline__ float wsum(float v) {
    #pragma unroll
    for (int o = 16; o; o >>= 1) v += __shfl_xor_sync(0xffffffffu, v, o);
    return v;
}

extern "C" __global__ void __launch_bounds__(256)
epi_kernel(const float* __restrict__ br,  const float* __restrict__ bn,
           const float* __restrict__ neps, const float* __restrict__ gum,
           float* __restrict__ out)
{
    __shared__ float imp_s[64], load_s[64];
    const int tid = threadIdx.x;
    const int wid = tid >> 5;
    const int lane = tid & 31;
    if (tid < 64) { imp_s[tid] = 0.f; load_s[tid] = 0.f; }
    __syncthreads();

    const int e0 = lane, e1 = lane + 32;
    const int row = blockIdx.x * 8 + wid;       // 1 row per warp, grid 2048

    const float* L = g_lg + (size_t)row * 128;
    float raw0 = L[e0] + br[e0],      raw1 = L[e1] + br[e1];
    float pre0 = L[64 + e0] + bn[e0], pre1 = L[64 + e1] + bn[e1];
    float sd0 = fmaxf(pre0, 0.f) + log1pf(expf(-fabsf(pre0))) + EPS_C;
    float sd1 = fmaxf(pre1, 0.f) + log1pf(expf(-fabsf(pre1))) + EPS_C;
    float nz0 = fmaf(neps[(size_t)row * NEXP + e0], sd0, raw0);
    float nz1 = fmaf(neps[(size_t)row * NEXP + e1], sd1, raw1);
    float g0 = gum[(size_t)row * NEXP + e0];
    float g1 = gum[(size_t)row * NEXP + e1];

    // ---- top-9 via redux.max on orderable keys (exact, tie -> lowest idx) ----
    uint32_t k0 = ordkey(nz0), k1 = ordkey(nz1);
    float h0 = 0.f, h1 = 0.f, thr = 0.f, m1 = 0.f;
    #pragma unroll 1
    for (int t = 0; t < KSEL; t++) {
        uint32_t M = redux_max(k0 > k1 ? k0 : k1);
        if (t == 0) m1 = ordinv(M);
        thr = ordinv(M);
        unsigned b0 = __ballot_sync(0xffffffffu, k0 == M);
        unsigned b1 = __ballot_sync(0xffffffffu, k1 == M);
        if (b0) {
            if (lane == __ffs(b0) - 1) { h0 = 1.f; k0 = 0u; }
        } else {
            if (lane == __ffs(b1) - 1) { h1 = 1.f; k1 = 0u; }
        }
    }

    // ---- softmax maxes via redux, sums via shfl ----
    float m2 = ordinv(redux_max(ordkey(fmaxf(nz0 + g0, nz1 + g1))));
    float m3 = ordinv(redux_max(ordkey(fmaxf(raw0, raw1))));
    float E10 = expf(nz0 - m1),      E11 = expf(nz1 - m1);
    float E20 = expf(nz0 + g0 - m2), E21 = expf(nz1 + g1 - m2);
    float E30 = expf(raw0 - m3),     E31 = expf(raw1 - m3);
    float i1 = 1.f / wsum(E10 + E11);
    float i2 = 1.f / wsum(E20 + E21);
    float i3 = 1.f / wsum(E30 + E31);

    float ms0 = E20 * i2, ms1 = E21 * i2;
    float* om  = out + (size_t)row * NEXP;
    float* orp = out + (size_t)N_TOK * NEXP + (size_t)row * NEXP;
    om[e0]  = (h0 - ms0) + ms0;
    om[e1]  = (h1 - ms1) + ms1;
    orp[e0] = E10 * i1;
    orp[e1] = E11 * i1;

    float imp0 = E30 * i3, imp1 = E31 * i3;
    float z0 = (thr - raw0) / sd0, z1 = (thr - raw1) / sd1;
    float ld0 = 0.5f * (1.f - erff(z0 * INV_SIG_SQRT2));
    float ld1 = 0.5f * (1.f - erff(z1 * INV_SIG_SQRT2));

    atomicAdd(&imp_s[e0], imp0);
    atomicAdd(&imp_s[e1], imp1);
    atomicAdd(&load_s[e0], ld0);
    atomicAdd(&load_s[e1], ld1);
    __syncthreads();
    if (tid < 64) {
        atomicAdd(out + 2 * (size_t)N_TOK * NEXP + tid,        imp_s[tid]);
        atomicAdd(out + 2 * (size_t)N_TOK * NEXP + NEXP + tid, load_s[tid]);
    }
}

extern "C" void kernel_launch(void* const* d_in, const int* in_sizes, int n_in,
                              void* d_out, int out_size)
{
    const float* x    = (const float*)d_in[0];
    const float* Wr   = (const float*)d_in[1];
    const float* br   = (const float*)d_in[2];
    const float* Wn   = (const float*)d_in[3];
    const float* bn   = (const float*)d_in[4];
    const float* neps = (const float*)d_in[5];
    const float* gum  = (const float*)d_in[6];
    float* out = (float*)d_out;

    cudaMemsetAsync(out + 2 * (size_t)N_TOK * NEXP, 0, 2 * NEXP * sizeof(float));

    cudaFuncSetAttribute(gemm_kernel,
                         cudaFuncAttributeMaxDynamicSharedMemorySize, SMEM_BYTES);
    gemm_kernel<<<GRID, 256, SMEM_BYTES>>>(x, Wr, Wn);

    epi_kernel<<<N_TOK / 8, 256>>>(br, bn, neps, gum, out);
}

// round 11
// speedup vs baseline: 1.1883x; 1.1883x over previous
#include <cuda_runtime.h>
#include <math.h>
#include <stdint.h>

#define N_TOK 16384
#define DIM   2048
#define NEXP  64
#define KSEL  9
#define EPS_C 0.01f
#define INV_SIG_SQRT2 45.254833995939045f

#define BM 112
#define GRID 147                   // ceil(16384/112)
#define BK 32
#define NCHUNK (DIM / BK)          // 64
#define NSTAGE 4
#define XTS 36                     // x smem row stride (u32)
#define XTILE (BM * XTS)           // 4032 u32
#define WTILE (BK * 128)           // 4096 u32
#define STAGEU (XTILE + WTILE)     // 8128 u32 = 32512 B
#define SMEM_BYTES (NSTAGE * STAGEU * 4)   // 130048 B
#define XV4 (BM * 8)               // 896 float4 per x stage

// logits scratch: [row][128] (0-63 raw dot, 64-127 noise-pre dot) = 8 MB
__device__ __align__(16) float g_lg[(size_t)N_TOK * 128];

__device__ __forceinline__ unsigned long long pack_dup(float a) {
    unsigned long long r;
    unsigned ai = __float_as_uint(a);
    asm("mov.b64 %0, {%1, %1};" : "=l"(r) : "r"(ai));
    return r;
}
__device__ __forceinline__ uint32_t smem_u32(const void* p) {
    uint32_t a;
    asm("{ .reg .u64 t; cvta.to.shared.u64 t, %1; cvt.u32.u64 %0, t; }"
        : "=r"(a) : "l"(p));
    return a;
}
__device__ __forceinline__ void cp16(uint32_t dst, const void* src) {
    asm volatile("cp.async.ca.shared.global [%0], [%1], 16;"
                 :: "r"(dst), "l"(src) : "memory");
}

// ---------------- GEMM: fp32 FFMA2, 112x128 per CTA, 147 CTAs (1/SM) ----------------
// (round-8 proven configuration, verbatim)
extern "C" __global__ void __launch_bounds__(256, 1)
gemm_kernel(const float* __restrict__ x, const float* __restrict__ Wr,
            const float* __restrict__ Wn)
{
    extern __shared__ uint32_t smu[];
    const uint32_t sbase = smem_u32(smu);
    const int tid = threadIdx.x;
    const int ty  = tid >> 4;        // 0..15 -> rows 7ty..7ty+6
    const int tx  = tid & 15;        // col pairs 2tx+32j
    const int row0 = blockIdx.x * BM;

    // ---- x cp.async map: 896 float4 over 256 threads x 4 iters (guarded) ----
    const float* xsrc[4];
    uint32_t     xoff[4];
    bool         xact[4];
    #pragma unroll
    for (int i = 0; i < 4; i++) {
        int idx = tid + 256 * i;
        xact[i] = (idx < XV4);
        int r = idx >> 3, seg = idx & 7;
        if (!xact[i]) { r = 0; seg = 0; }
        int grow = row0 + r; if (grow > N_TOK - 1) grow = N_TOK - 1;  // tail clamp
        xsrc[i] = x + (size_t)grow * DIM + seg * 4;
        xoff[i] = (uint32_t)((r * XTS + seg * 4) * 4);
    }
    // ---- W cp.async map ----
    const int wk = tid >> 5, wq = tid & 31;
    const int wcol = wq * 4;
    const float* wsrcbase = (wcol < 64) ? (Wr + wcol) : (Wn + wcol - 64);

    unsigned long long acc[7][4];
    #pragma unroll
    for (int i = 0; i < 7; i++)
        #pragma unroll
        for (int j = 0; j < 4; j++) acc[i][j] = 0ULL;

    auto issue = [&](int c) {
        uint32_t buf = sbase + (uint32_t)((c & (NSTAGE - 1)) * STAGEU * 4);
        #pragma unroll
        for (int i = 0; i < 4; i++)
            if (xact[i]) cp16(buf + xoff[i], xsrc[i] + c * BK);
        #pragma unroll
        for (int i = 0; i < 4; i++) {
            int kk = wk + 8 * i;
            cp16(buf + (uint32_t)((XTILE + kk * 128 + wcol) * 4),
                 wsrcbase + (size_t)(c * BK + kk) * NEXP);
        }
    };

    // prologue: stages 0..2
    #pragma unroll
    for (int p = 0; p < NSTAGE - 1; p++) {
        issue(p);
        asm volatile("cp.async.commit_group;" ::: "memory");
    }

    #pragma unroll 1
    for (int c = 0; c < NCHUNK; c++) {
        // peeled waits: per-thread pending groups shrink at the tail
        if (c < NCHUNK - 2)
            asm volatile("cp.async.wait_group 2;" ::: "memory");
        else if (c == NCHUNK - 2)
            asm volatile("cp.async.wait_group 1;" ::: "memory");
        else
            asm volatile("cp.async.wait_group 0;" ::: "memory");
        __syncthreads();
        if (c + NSTAGE - 1 < NCHUNK) {
            issue(c + NSTAGE - 1);              // stage (c-1)&3: readers passed barrier
            asm volatile("cp.async.commit_group;" ::: "memory");
        }

        const uint32_t* buf = smu + (c & (NSTAGE - 1)) * STAGEU;
        const float* xs = (const float*)buf;
        const float* ws = (const float*)(buf + XTILE);
        #pragma unroll 4
        for (int kk = 0; kk < BK; kk++) {
            unsigned long long b2[4];
            #pragma unroll
            for (int j = 0; j < 4; j++)
                b2[j] = *(const unsigned long long*)(ws + kk * 128 + 2 * tx + 32 * j);
            unsigned long long a2[7];
            #pragma unroll
            for (int i = 0; i < 7; i++)
                a2[i] = pack_dup(xs[(7 * ty + i) * XTS + kk]);
            #pragma unroll
            for (int i = 0; i < 7; i++)
                #pragma unroll
                for (int j = 0; j < 4; j++)
                    asm("fma.rn.f32x2 %0, %1, %2, %0;"
                        : "+l"(acc[i][j]) : "l"(a2[i]), "l"(b2[j]));
        }
        // no bottom sync: top wait+sync of next iteration orders stage reuse
    }

    // ---- write logits (STG.64, coalesced); guard tail CTA ----
    #pragma unroll
    for (int i = 0; i < 7; i++) {
        int row = row0 + 7 * ty + i;
        if (row < N_TOK) {
            #pragma unroll
            for (int j = 0; j < 4; j++)
                *(unsigned long long*)(g_lg + (size_t)row * 128 + 2 * tx + 32 * j)
                    = acc[i][j];
        }
    }
}

// ---------------- epilogue: 1 row per warp, redux-based top-9 ----------------
// (round-10 proven configuration, verbatim)
__device__ __forceinline__ uint32_t redux_max(uint32_t v) {
    uint32_t r;
    asm("redux.sync.max.u32 %0, %1, 0xffffffff;" : "=r"(r) : "r"(v));
    return r;
}
__device__ __forceinline__ uint32_t ordkey(float f) {
    uint32_t u = __float_as_uint(f);
    return ((int)u < 0) ? ~u : (u | 0x80000000u);
}
__device__ __forceinline__ float ordinv(uint32_t k) {
    return __uint_as_float(((int)k < 0) ? (k ^ 0x80000000u) : ~k);
}
__device__ __forceinline__ float wsum(float v) {
    #pragma unroll
    for (int o = 16; o; o >>= 1) v += __shfl_xor_sync(0xffffffffu, v, o);
    return v;
}

extern "C" __global__ void __launch_bounds__(256)
epi_kernel(const float* __restrict__ br,  const float* __restrict__ bn,
           const float* __restrict__ neps, const float* __restrict__ gum,
           float* __restrict__ out)
{
    __shared__ float imp_s[64], load_s[64];
    const int tid = threadIdx.x;
    const int wid = tid >> 5;
    const int lane = tid & 31;
    if (tid < 64) { imp_s[tid] = 0.f; load_s[tid] = 0.f; }
    __syncthreads();

    const int e0 = lane, e1 = lane + 32;
    const int row = blockIdx.x * 8 + wid;       // 1 row per warp, grid 2048

    const float* L = g_lg + (size_t)row * 128;
    float raw0 = L[e0] + br[e0],      raw1 = L[e1] + br[e1];
    float pre0 = L[64 + e0] + bn[e0], pre1 = L[64 + e1] + bn[e1];
    float sd0 = fmaxf(pre0, 0.f) + log1pf(expf(-fabsf(pre0))) + EPS_C;
    float sd1 = fmaxf(pre1, 0.f) + log1pf(expf(-fabsf(pre1))) + EPS_C;
    float nz0 = fmaf(neps[(size_t)row * NEXP + e0], sd0, raw0);
    float nz1 = fmaf(neps[(size_t)row * NEXP + e1], sd1, raw1);
    float g0 = gum[(size_t)row * NEXP + e0];
    float g1 = gum[(size_t)row * NEXP + e1];

    // ---- top-9 via redux.max on orderable keys (exact, tie -> lowest idx) ----
    uint32_t k0 = ordkey(nz0), k1 = ordkey(nz1);
    float h0 = 0.f, h1 = 0.f, thr = 0.f, m1 = 0.f;
    #pragma unroll 1
    for (int t = 0; t < KSEL; t++) {
        uint32_t M = redux_max(k0 > k1 ? k0 : k1);
        if (t == 0) m1 = ordinv(M);
        thr = ordinv(M);
        unsigned b0 = __ballot_sync(0xffffffffu, k0 == M);
        unsigned b1 = __ballot_sync(0xffffffffu, k1 == M);
        if (b0) {
            if (lane == __ffs(b0) - 1) { h0 = 1.f; k0 = 0u; }
        } else {
            if (lane == __ffs(b1) - 1) { h1 = 1.f; k1 = 0u; }
        }
    }

    // ---- softmax maxes via redux, sums via shfl ----
    float m2 = ordinv(redux_max(ordkey(fmaxf(nz0 + g0, nz1 + g1))));
    float m3 = ordinv(redux_max(ordkey(fmaxf(raw0, raw1))));
    float E10 = expf(nz0 - m1),      E11 = expf(nz1 - m1);
    float E20 = expf(nz0 + g0 - m2), E21 = expf(nz1 + g1 - m2);
    float E30 = expf(raw0 - m3),     E31 = expf(raw1 - m3);
    float i1 = 1.f / wsum(E10 + E11);
    float i2 = 1.f / wsum(E20 + E21);
    float i3 = 1.f / wsum(E30 + E31);

    float ms0 = E20 * i2, ms1 = E21 * i2;
    float* om  = out + (size_t)row * NEXP;
    float* orp = out + (size_t)N_TOK * NEXP + (size_t)row * NEXP;
    om[e0]  = (h0 - ms0) + ms0;
    om[e1]  = (h1 - ms1) + ms1;
    orp[e0] = E10 * i1;
    orp[e1] = E11 * i1;

    float imp0 = E30 * i3, imp1 = E31 * i3;
    float z0 = (thr - raw0) / sd0, z1 = (thr - raw1) / sd1;
    float ld0 = 0.5f * (1.f - erff(z0 * INV_SIG_SQRT2));
    float ld1 = 0.5f * (1.f - erff(z1 * INV_SIG_SQRT2));

    atomicAdd(&imp_s[e0], imp0);
    atomicAdd(&imp_s[e1], imp1);
    atomicAdd(&load_s[e0], ld0);
    atomicAdd(&load_s[e1], ld1);
    __syncthreads();
    if (tid < 64) {
        atomicAdd(out + 2 * (size_t)N_TOK * NEXP + tid,        imp_s[tid]);
        atomicAdd(out + 2 * (size_t)N_TOK * NEXP + NEXP + tid, load_s[tid]);
    }
}

extern "C" void kernel_launch(void* const* d_in, const int* in_sizes, int n_in,
                              void* d_out, int out_size)
{
    const float* x    = (const float*)d_in[0];
    const float* Wr   = (const float*)d_in[1];
    const float* br   = (const float*)d_in[2];
    const float* Wn   = (const float*)d_in[3];
    const float* bn   = (const float*)d_in[4];
    const float* neps = (const float*)d_in[5];
    const float* gum  = (const float*)d_in[6];
    float* out = (float*)d_out;

    cudaMemsetAsync(out + 2 * (size_t)N_TOK * NEXP, 0, 2 * NEXP * sizeof(float));

    cudaFuncSetAttribute(gemm_kernel,
                         cudaFuncAttributeMaxDynamicSharedMemorySize, SMEM_BYTES);
    gemm_kernel<<<GRID, 256, SMEM_BYTES>>>(x, Wr, Wn);

    epi_kernel<<<N_TOK / 8, 256>>>(br, bn, neps, gum, out);
}